// round 14
// baseline (speedup 1.0000x reference)
#include <cuda_runtime.h>
#include <math.h>

// Problem constants
#define NB    8192
#define NS    128
#define NT    64
#define NOBS  64
#define NLAT  128
#define NENC  256
#define NODE  256
#define NDEC  256
#define NSUB  4

#define TM       64     // batch rows per CTA
#define NTHREADS 512    // 16 warps, split over rows x cols (4x4 / 8x2 grids)

// padded leading dims: lda % 32 == 4 (floats) -> row pairs hit disjoint banks
#define LDA_Z 132
#define LDA_G 260
#define LDA_A 324
#define LDA_B 132       // ZB pad

typedef unsigned long long u64;

static __device__ float g_z0[NB * NLAT];   // z0 handoff (static scratch)

__device__ __forceinline__ u64 pk2(float x, float y) {
    u64 r; asm("mov.b64 %0, {%1, %2};" : "=l"(r) : "f"(x), "f"(y)); return r;
}
__device__ __forceinline__ void upk2(float& x, float& y, u64 v) {
    asm("mov.b64 {%0, %1}, %2;" : "=f"(x), "=f"(y) : "l"(v));
}
// packed fp32x2 fma -> SASS FFMA2 (2x fp32 rate)
__device__ __forceinline__ void ffma2(u64& d, u64 a, u64 b) {
    asm("fma.rn.f32x2 %0, %1, %2, %0;" : "+l"(d) : "l"(a), "l"(b));
}
__device__ __forceinline__ float f4c(const float4 v, int k) {
    return k == 0 ? v.x : k == 1 ? v.y : k == 2 ? v.z : v.w;
}
// hardware tanh (MUFU-class). ODE f-evals only; encoder keeps exact tanhf.
__device__ __forceinline__ float tanh_fast(float x) {
    float y; asm("tanh.approx.f32 %0, %1;" : "=f"(y) : "f"(x)); return y;
}

// Split-M+N warp GEMM with batched B loads (R8/R11 geometry, unroll-4 k-loop).
// Thread tile: NR rows {rbase + RS*i} x 2*PAIRS cols [col0,...).
// A: within a warp only 2 distinct rows per LDS.128 (h-split, lda%32==4 ->
// disjoint banks). B: 16 lanes read a contiguous slab, h-halves broadcast.
template<int NR, int RS, int PAIRS>
__device__ __forceinline__ void wgemmN(
    const float* __restrict__ As, int lda, int K,
    const float* __restrict__ Bg, int ldb, int col0,
    int rbase, u64 (&acc)[NR][PAIRS])
{
    #pragma unroll 4
    for (int k4 = 0; k4 < (K >> 2); ++k4) {
        // ---- batched B loads for all 4 kk of this k4 ----
        u64 bq[4][PAIRS];
        #pragma unroll
        for (int kk = 0; kk < 4; ++kk) {
            const float* bp = Bg + (size_t)(k4 * 4 + kk) * ldb + col0;
            if constexpr (PAIRS == 2) {
                ulonglong2 q = __ldg(reinterpret_cast<const ulonglong2*>(bp));
                bq[kk][0] = q.x; bq[kk][1] = q.y;
            } else {
                bq[kk][0] = __ldg(reinterpret_cast<const u64*>(bp));
            }
        }
        // ---- A fragments ----
        float4 av[NR];
        #pragma unroll
        for (int i = 0; i < NR; ++i)
            av[i] = *reinterpret_cast<const float4*>(&As[(rbase + RS * i) * lda + (k4 << 2)]);
        // ---- fma schedule ----
        #pragma unroll
        for (int kk = 0; kk < 4; ++kk) {
            #pragma unroll
            for (int i = 0; i < NR; ++i) {
                float a = f4c(av[i], kk);
                u64 aa = pk2(a, a);
                #pragma unroll
                for (int j = 0; j < PAIRS; ++j) ffma2(acc[i][j], aa, bq[kk][j]);
            }
        }
    }
}

// ==================== Persistent encoder: 128 RNN steps + head ====================
__global__ void __launch_bounds__(NTHREADS)
encoder_kernel(const float* __restrict__ obs,
               const float* __restrict__ Wi2h, const float* __restrict__ bi2h,
               const float* __restrict__ Wh2o, const float* __restrict__ bh2o,
               const float* __restrict__ eps, float* __restrict__ out)
{
    extern __shared__ float A[];                 // [64][324]: [x(64) | h(256) | pad]
    int tid = threadIdx.x, lane = tid & 31, w = tid >> 5;
    int h  = lane >> 4;                          // 0..1
    int cg = lane & 15;                          // 0..15
    int MG = w & 3, NG = w >> 2;                 // 4 x 4 warp grid
    int rbase = MG * 16 + h;                     // rows rbase + 2i, i=0..7
    int col1  = NG * 64 + cg * 4;                // 4-col slab in 256-col outputs
    int m0 = blockIdx.x * TM;

    // zero the h region
    for (int i = tid; i < TM * NENC / 4; i += NTHREADS) {
        int m = i >> 6, k = (i & 63) << 2;
        *reinterpret_cast<float4*>(&A[m * LDA_A + NOBS + k]) = make_float4(0, 0, 0, 0);
    }
    float4 bi = __ldg(reinterpret_cast<const float4*>(&bi2h[col1]));

    // load x for t = NS-1  (64 rows x 16 float4 = 1024 float4, 2 per thread)
    #pragma unroll
    for (int j = 0; j < 2; ++j) {
        int idx = tid + j * NTHREADS;
        int row = idx >> 4, f = idx & 15;
        *reinterpret_cast<float4*>(&A[row * LDA_A + f * 4]) =
            __ldg(reinterpret_cast<const float4*>(
                &obs[((size_t)(m0 + row) * NS + (NS - 1)) * NOBS + f * 4]));
    }
    __syncthreads();

    #pragma unroll 1
    for (int s = 0; s < NS; ++s) {
        u64 acc[8][2];
        #pragma unroll
        for (int i = 0; i < 8; ++i) { acc[i][0] = 0; acc[i][1] = 0; }
        wgemmN<8, 2, 2>(A, LDA_A, NOBS + NENC, Wi2h, NENC, col1, rbase, acc);

        // prefetch next step's x while waiting at the barrier
        float4 xp[2];
        if (s + 1 < NS) {
            #pragma unroll
            for (int j = 0; j < 2; ++j) {
                int idx = tid + j * NTHREADS;
                int row = idx >> 4, f = idx & 15;
                xp[j] = __ldg(reinterpret_cast<const float4*>(
                    &obs[((size_t)(m0 + row) * NS + (NS - 2 - s)) * NOBS + f * 4]));
            }
        }
        __syncthreads();   // all A reads done

        #pragma unroll
        for (int i = 0; i < 8; ++i) {
            int row = rbase + 2 * i;
            float c0, c1, c2, c3;
            upk2(c0, c1, acc[i][0]); upk2(c2, c3, acc[i][1]);
            *reinterpret_cast<float4*>(&A[row * LDA_A + NOBS + col1]) =
                make_float4(tanhf(c0 + bi.x), tanhf(c1 + bi.y),
                            tanhf(c2 + bi.z), tanhf(c3 + bi.w));
        }
        if (s + 1 < NS) {
            #pragma unroll
            for (int j = 0; j < 2; ++j) {
                int idx = tid + j * NTHREADS;
                int row = idx >> 4, f = idx & 15;
                *reinterpret_cast<float4*>(&A[row * LDA_A + f * 4]) = xp[j];
            }
        }
        __syncthreads();
    }

    // head: O = h @ Wh2o + b  (into A cols 0..255 after reads complete)
    u64 acc[8][2];
    #pragma unroll
    for (int i = 0; i < 8; ++i) { acc[i][0] = 0; acc[i][1] = 0; }
    wgemmN<8, 2, 2>(A + NOBS, LDA_A, NENC, Wh2o, 2 * NLAT, col1, rbase, acc);
    float4 bh = __ldg(reinterpret_cast<const float4*>(&bh2o[col1]));
    __syncthreads();
    #pragma unroll
    for (int i = 0; i < 8; ++i) {
        int row = rbase + 2 * i;
        float c0, c1, c2, c3;
        upk2(c0, c1, acc[i][0]); upk2(c2, c3, acc[i][1]);
        *reinterpret_cast<float4*>(&A[row * LDA_A + col1]) =
            make_float4(c0 + bh.x, c1 + bh.y, c2 + bh.z, c3 + bh.w);
    }
    __syncthreads();

    // z0 = mean + eps * exp(0.5*logvar); emit mean/logvar
    const size_t MEAN_OFF = (size_t)NT * NB * NOBS;
    const size_t LV_OFF   = MEAN_OFF + (size_t)NB * NLAT;
    for (int i = tid; i < TM * NLAT; i += NTHREADS) {
        int m = i >> 7, l = i & (NLAT - 1);
        float mean = A[m * LDA_A + l];
        float lv   = A[m * LDA_A + NLAT + l];
        float z0   = mean + __ldg(&eps[(size_t)(m0 + m) * NLAT + l]) * expf(0.5f * lv);
        g_z0[(size_t)(m0 + m) * NLAT + l] = z0;
        out[MEAN_OFF + (size_t)(m0 + m) * NLAT + l] = mean;
        out[LV_OFF   + (size_t)(m0 + m) * NLAT + l] = lv;
    }
}

// ==================== Persistent ODE: 63x4 RK4 substeps + 64 decodes ====================
__global__ void __launch_bounds__(NTHREADS)
ode_kernel(const float* __restrict__ W1,  const float* __restrict__ b1,
           const float* __restrict__ W2,  const float* __restrict__ b2,
           const float* __restrict__ Wd1, const float* __restrict__ bd1,
           const float* __restrict__ Wd2, const float* __restrict__ bd2,
           const float* __restrict__ ptimes, float* __restrict__ out)
{
    extern __shared__ float sm[];
    float* Z  = sm;                                  // [64][132] stage input zc
    float* G  = sm + TM * LDA_Z;                     // [64][260] hidden activations
    float* ZB = sm + TM * LDA_Z + TM * LDA_G;        // [64][132] substep base z
    int tid = threadIdx.x, lane = tid & 31, w = tid >> 5;
    int h  = lane >> 4;                              // 0..1
    int cg = lane & 15;                              // 0..15
    // 256-col GEMMs: 4x4 warp grid, thread = 8 rows (stride 2) x 4 cols
    int MG  = w & 3,  NG  = w >> 2;
    int rb1 = MG * 16 + h;
    int col1 = NG * 64 + cg * 4;
    // 128/64-col GEMMs: 8x2 warp grid, thread = 4 rows (stride 1) x 4(/2) cols
    int MG2 = w & 7,  NG2 = w >> 3;
    int rb2 = MG2 * 8 + h * 4;
    int col2 = NG2 * 64 + cg * 4;    // 128-col GEMM (4 cols/thread)
    int colD = NG2 * 32 + cg * 2;    // 64-col decode (2 cols/thread)
    int m0 = blockIdx.x * TM;

    float4 b1v  = __ldg(reinterpret_cast<const float4*>(&b1[col1]));
    float4 bd1v = __ldg(reinterpret_cast<const float4*>(&bd1[col1]));
    float4 b2v  = __ldg(reinterpret_cast<const float4*>(&b2[col2]));
    float2 bd2v = __ldg(reinterpret_cast<const float2*>(&bd2[colD]));

    // current z: this thread owns rows {rb2+i, i=0..3} x cols [col2, col2+4)
    float zr[4][4];
    #pragma unroll
    for (int i = 0; i < 4; ++i) {
        int row = rb2 + i;
        float4 v = *reinterpret_cast<const float4*>(&g_z0[(size_t)(m0 + row) * NLAT + col2]);
        zr[i][0]=v.x; zr[i][1]=v.y; zr[i][2]=v.z; zr[i][3]=v.w;
        *reinterpret_cast<float4*>(&Z[row * LDA_Z + col2]) = v;
    }
    __syncthreads();

    auto decode = [&](int tindex) {
        u64 a1[8][2];
        #pragma unroll
        for (int i = 0; i < 8; ++i) { a1[i][0] = 0; a1[i][1] = 0; }
        wgemmN<8, 2, 2>(Z, LDA_Z, NLAT, Wd1, NDEC, col1, rb1, a1);
        #pragma unroll
        for (int i = 0; i < 8; ++i) {
            int row = rb1 + 2 * i;
            float c0, c1, c2, c3;
            upk2(c0, c1, a1[i][0]); upk2(c2, c3, a1[i][1]);
            *reinterpret_cast<float4*>(&G[row * LDA_G + col1]) =
                make_float4(fmaxf(c0 + bd1v.x, 0.f), fmaxf(c1 + bd1v.y, 0.f),
                            fmaxf(c2 + bd1v.z, 0.f), fmaxf(c3 + bd1v.w, 0.f));
        }
        __syncthreads();
        u64 a2[4][1];
        #pragma unroll
        for (int i = 0; i < 4; ++i) a2[i][0] = 0;
        wgemmN<4, 1, 1>(G, LDA_G, NDEC, Wd2, NOBS, colD, rb2, a2);
        #pragma unroll
        for (int i = 0; i < 4; ++i) {
            int row = rb2 + i;
            float x, y; upk2(x, y, a2[i][0]);
            *reinterpret_cast<float2*>(
                &out[((size_t)tindex * NB + (m0 + row)) * NOBS + colD]) =
                make_float2(x + bd2v.x, y + bd2v.y);
        }
        __syncthreads();   // G reads done before next stage overwrites G
    };

    decode(0);

    #pragma unroll 1
    for (int iv = 0; iv < NT - 1; ++iv) {
        float dt = (__ldg(&ptimes[iv + 1]) - __ldg(&ptimes[iv])) * (1.0f / NSUB);
        #pragma unroll 1
        for (int ss = 0; ss < NSUB; ++ss) {
            // stash substep base z in padded SMEM (thread-private cells)
            #pragma unroll
            for (int i = 0; i < 4; ++i)
                *reinterpret_cast<float4*>(&ZB[(rb2 + i) * LDA_B + col2]) =
                    make_float4(zr[i][0], zr[i][1], zr[i][2], zr[i][3]);

            #pragma unroll 1
            for (int s = 0; s < 4; ++s) {
                float wt = (s == 0 || s == 3) ? dt * (1.0f / 6.0f) : dt * (1.0f / 3.0f);
                float ci = (s == 2) ? dt : 0.5f * dt;

                // g = tanh(zc @ W1 + b1)   [hardware tanh.approx]
                u64 a1[8][2];
                #pragma unroll
                for (int i = 0; i < 8; ++i) { a1[i][0] = 0; a1[i][1] = 0; }
                wgemmN<8, 2, 2>(Z, LDA_Z, NLAT, W1, NODE, col1, rb1, a1);
                #pragma unroll
                for (int i = 0; i < 8; ++i) {
                    int row = rb1 + 2 * i;
                    float c0, c1, c2, c3;
                    upk2(c0, c1, a1[i][0]); upk2(c2, c3, a1[i][1]);
                    *reinterpret_cast<float4*>(&G[row * LDA_G + col1]) =
                        make_float4(tanh_fast(c0 + b1v.x), tanh_fast(c1 + b1v.y),
                                    tanh_fast(c2 + b1v.z), tanh_fast(c3 + b1v.w));
                }
                __syncthreads();   // all GEMM1 (Z reads) + G writes complete

                // k = g @ W2 + b2 ; fold into RK4 accumulator and next stage input
                u64 a2[4][2];
                #pragma unroll
                for (int i = 0; i < 4; ++i) { a2[i][0] = 0; a2[i][1] = 0; }
                wgemmN<4, 1, 2>(G, LDA_G, NODE, W2, NLAT, col2, rb2, a2);
                #pragma unroll
                for (int i = 0; i < 4; ++i) {
                    int row = rb2 + i;
                    float k0, k1, k2, k3;
                    upk2(k0, k1, a2[i][0]); upk2(k2, k3, a2[i][1]);
                    k0 += b2v.x; k1 += b2v.y; k2 += b2v.z; k3 += b2v.w;
                    zr[i][0] += wt * k0; zr[i][1] += wt * k1;
                    zr[i][2] += wt * k2; zr[i][3] += wt * k3;
                    float4 v;
                    if (s < 3) {
                        float4 zb = *reinterpret_cast<const float4*>(&ZB[row * LDA_B + col2]);
                        v = make_float4(zb.x + ci * k0, zb.y + ci * k1,
                                        zb.z + ci * k2, zb.w + ci * k3);
                    } else {
                        v = make_float4(zr[i][0], zr[i][1], zr[i][2], zr[i][3]);
                    }
                    *reinterpret_cast<float4*>(&Z[row * LDA_Z + col2]) = v;
                }
                __syncthreads();   // Z consistent before next GEMM1 / decode
            }
        }
        decode(iv + 1);
    }
}

// -------------------- Launcher --------------------
extern "C" void kernel_launch(void* const* d_in, const int* in_sizes, int n_in,
                              void* d_out, int out_size)
{
    const float* obs    = (const float*)d_in[0];
    /* d_in[1] observed_times: unused by the reference computation */
    const float* ptimes = (const float*)d_in[2];
    const float* eps    = (const float*)d_in[3];
    const float* Wi2h   = (const float*)d_in[4];
    const float* bi2h   = (const float*)d_in[5];
    const float* Wh2o   = (const float*)d_in[6];
    const float* bh2o   = (const float*)d_in[7];
    const float* Wode1  = (const float*)d_in[8];
    const float* bode1  = (const float*)d_in[9];
    const float* Wode2  = (const float*)d_in[10];
    const float* bode2  = (const float*)d_in[11];
    const float* Wdec1  = (const float*)d_in[12];
    const float* bdec1  = (const float*)d_in[13];
    const float* Wdec2  = (const float*)d_in[14];
    const float* bdec2  = (const float*)d_in[15];
    float* out = (float*)d_out;

    const int SM_ENC = TM * LDA_A * 4;                               // 82944
    const int SM_ODE = (TM * LDA_Z + TM * LDA_G + TM * LDA_B) * 4;   // 134144

    cudaFuncSetAttribute(encoder_kernel, cudaFuncAttributeMaxDynamicSharedMemorySize, SM_ENC);
    cudaFuncSetAttribute(ode_kernel,     cudaFuncAttributeMaxDynamicSharedMemorySize, SM_ODE);

    dim3 grid(NB / TM);   // 128 CTAs

    encoder_kernel<<<grid, NTHREADS, SM_ENC>>>(obs, Wi2h, bi2h, Wh2o, bh2o, eps, out);
    ode_kernel<<<grid, NTHREADS, SM_ODE>>>(Wode1, bode1, Wode2, bode2,
                                           Wdec1, bdec1, Wdec2, bdec2, ptimes, out);
}

// round 15
// speedup vs baseline: 1.0018x; 1.0018x over previous
#include <cuda_runtime.h>
#include <math.h>

// Problem constants
#define NB    8192
#define NS    128
#define NT    64
#define NOBS  64
#define NLAT  128
#define NENC  256
#define NODE  256
#define NDEC  256
#define NSUB  4

#define TM       64     // batch rows per CTA
#define NTHREADS 512    // 16 warps, split over rows x cols (4x4 / 8x2 grids)

// padded leading dims: lda % 32 == 4 (floats) -> row pairs hit disjoint banks
#define LDA_Z 132
#define LDA_G 260
#define LDA_A 324
#define LDA_B 132       // ZB pad

typedef unsigned long long u64;

static __device__ float g_z0[NB * NLAT];   // z0 handoff (static scratch)

__device__ __forceinline__ u64 pk2(float x, float y) {
    u64 r; asm("mov.b64 %0, {%1, %2};" : "=l"(r) : "f"(x), "f"(y)); return r;
}
__device__ __forceinline__ void upk2(float& x, float& y, u64 v) {
    asm("mov.b64 {%0, %1}, %2;" : "=f"(x), "=f"(y) : "l"(v));
}
// packed fp32x2 fma -> SASS FFMA2 (2x fp32 rate)
__device__ __forceinline__ void ffma2(u64& d, u64 a, u64 b) {
    asm("fma.rn.f32x2 %0, %1, %2, %0;" : "+l"(d) : "l"(a), "l"(b));
}
__device__ __forceinline__ float f4c(const float4 v, int k) {
    return k == 0 ? v.x : k == 1 ? v.y : k == 2 ? v.z : v.w;
}
// hardware tanh (MUFU-class). ODE f-evals only; encoder keeps exact tanhf.
__device__ __forceinline__ float tanh_fast(float x) {
    float y; asm("tanh.approx.f32 %0, %1;" : "=f"(y) : "f"(x)); return y;
}

// Split-M+N warp GEMM with batched B loads (R8/R11 geometry, unroll-4 k-loop).
// Thread tile: NR rows {rbase + RS*i} x 2*PAIRS cols [col0,...).
// A: within a warp only 2 distinct rows per LDS.128 (h-split, lda%32==4 ->
// disjoint banks). B: 16 lanes read a contiguous slab, h-halves broadcast.
template<int NR, int RS, int PAIRS>
__device__ __forceinline__ void wgemmN(
    const float* __restrict__ As, int lda, int K,
    const float* __restrict__ Bg, int ldb, int col0,
    int rbase, u64 (&acc)[NR][PAIRS])
{
    #pragma unroll 4
    for (int k4 = 0; k4 < (K >> 2); ++k4) {
        // ---- batched B loads for all 4 kk of this k4 ----
        u64 bq[4][PAIRS];
        #pragma unroll
        for (int kk = 0; kk < 4; ++kk) {
            const float* bp = Bg + (size_t)(k4 * 4 + kk) * ldb + col0;
            if constexpr (PAIRS == 2) {
                ulonglong2 q = __ldg(reinterpret_cast<const ulonglong2*>(bp));
                bq[kk][0] = q.x; bq[kk][1] = q.y;
            } else {
                bq[kk][0] = __ldg(reinterpret_cast<const u64*>(bp));
            }
        }
        // ---- A fragments ----
        float4 av[NR];
        #pragma unroll
        for (int i = 0; i < NR; ++i)
            av[i] = *reinterpret_cast<const float4*>(&As[(rbase + RS * i) * lda + (k4 << 2)]);
        // ---- fma schedule ----
        #pragma unroll
        for (int kk = 0; kk < 4; ++kk) {
            #pragma unroll
            for (int i = 0; i < NR; ++i) {
                float a = f4c(av[i], kk);
                u64 aa = pk2(a, a);
                #pragma unroll
                for (int j = 0; j < PAIRS; ++j) ffma2(acc[i][j], aa, bq[kk][j]);
            }
        }
    }
}

// ==================== Persistent encoder: 128 RNN steps + head ====================
__global__ void __launch_bounds__(NTHREADS)
encoder_kernel(const float* __restrict__ obs,
               const float* __restrict__ Wi2h, const float* __restrict__ bi2h,
               const float* __restrict__ Wh2o, const float* __restrict__ bh2o,
               const float* __restrict__ eps, float* __restrict__ out)
{
    extern __shared__ float A[];                 // [64][324]: [x(64) | h(256) | pad]
    int tid = threadIdx.x, lane = tid & 31, w = tid >> 5;
    int h  = lane >> 4;                          // 0..1
    int cg = lane & 15;                          // 0..15
    int MG = w & 3, NG = w >> 2;                 // 4 x 4 warp grid
    int rbase = MG * 16 + h;                     // rows rbase + 2i, i=0..7
    int col1  = NG * 64 + cg * 4;                // 4-col slab in 256-col outputs
    int m0 = blockIdx.x * TM;

    // zero the h region
    for (int i = tid; i < TM * NENC / 4; i += NTHREADS) {
        int m = i >> 6, k = (i & 63) << 2;
        *reinterpret_cast<float4*>(&A[m * LDA_A + NOBS + k]) = make_float4(0, 0, 0, 0);
    }
    float4 bi = __ldg(reinterpret_cast<const float4*>(&bi2h[col1]));

    // load x for t = NS-1  (64 rows x 16 float4 = 1024 float4, 2 per thread)
    #pragma unroll
    for (int j = 0; j < 2; ++j) {
        int idx = tid + j * NTHREADS;
        int row = idx >> 4, f = idx & 15;
        *reinterpret_cast<float4*>(&A[row * LDA_A + f * 4]) =
            __ldg(reinterpret_cast<const float4*>(
                &obs[((size_t)(m0 + row) * NS + (NS - 1)) * NOBS + f * 4]));
    }
    __syncthreads();

    #pragma unroll 1
    for (int s = 0; s < NS; ++s) {
        u64 acc[8][2];
        #pragma unroll
        for (int i = 0; i < 8; ++i) { acc[i][0] = 0; acc[i][1] = 0; }
        wgemmN<8, 2, 2>(A, LDA_A, NOBS + NENC, Wi2h, NENC, col1, rbase, acc);

        // prefetch next step's x while waiting at the barrier
        float4 xp[2];
        if (s + 1 < NS) {
            #pragma unroll
            for (int j = 0; j < 2; ++j) {
                int idx = tid + j * NTHREADS;
                int row = idx >> 4, f = idx & 15;
                xp[j] = __ldg(reinterpret_cast<const float4*>(
                    &obs[((size_t)(m0 + row) * NS + (NS - 2 - s)) * NOBS + f * 4]));
            }
        }
        __syncthreads();   // all A reads done

        #pragma unroll
        for (int i = 0; i < 8; ++i) {
            int row = rbase + 2 * i;
            float c0, c1, c2, c3;
            upk2(c0, c1, acc[i][0]); upk2(c2, c3, acc[i][1]);
            *reinterpret_cast<float4*>(&A[row * LDA_A + NOBS + col1]) =
                make_float4(tanhf(c0 + bi.x), tanhf(c1 + bi.y),
                            tanhf(c2 + bi.z), tanhf(c3 + bi.w));
        }
        if (s + 1 < NS) {
            #pragma unroll
            for (int j = 0; j < 2; ++j) {
                int idx = tid + j * NTHREADS;
                int row = idx >> 4, f = idx & 15;
                *reinterpret_cast<float4*>(&A[row * LDA_A + f * 4]) = xp[j];
            }
        }
        __syncthreads();
    }

    // head: O = h @ Wh2o + b  (into A cols 0..255 after reads complete)
    u64 acc[8][2];
    #pragma unroll
    for (int i = 0; i < 8; ++i) { acc[i][0] = 0; acc[i][1] = 0; }
    wgemmN<8, 2, 2>(A + NOBS, LDA_A, NENC, Wh2o, 2 * NLAT, col1, rbase, acc);
    float4 bh = __ldg(reinterpret_cast<const float4*>(&bh2o[col1]));
    __syncthreads();
    #pragma unroll
    for (int i = 0; i < 8; ++i) {
        int row = rbase + 2 * i;
        float c0, c1, c2, c3;
        upk2(c0, c1, acc[i][0]); upk2(c2, c3, acc[i][1]);
        *reinterpret_cast<float4*>(&A[row * LDA_A + col1]) =
            make_float4(c0 + bh.x, c1 + bh.y, c2 + bh.z, c3 + bh.w);
    }
    __syncthreads();

    // z0 = mean + eps * exp(0.5*logvar); emit mean/logvar
    const size_t MEAN_OFF = (size_t)NT * NB * NOBS;
    const size_t LV_OFF   = MEAN_OFF + (size_t)NB * NLAT;
    for (int i = tid; i < TM * NLAT; i += NTHREADS) {
        int m = i >> 7, l = i & (NLAT - 1);
        float mean = A[m * LDA_A + l];
        float lv   = A[m * LDA_A + NLAT + l];
        float z0   = mean + __ldg(&eps[(size_t)(m0 + m) * NLAT + l]) * expf(0.5f * lv);
        g_z0[(size_t)(m0 + m) * NLAT + l] = z0;
        out[MEAN_OFF + (size_t)(m0 + m) * NLAT + l] = mean;
        out[LV_OFF   + (size_t)(m0 + m) * NLAT + l] = lv;
    }
}

// ==================== Persistent ODE: 63x4 RK4 substeps + 64 decodes ====================
__global__ void __launch_bounds__(NTHREADS)
ode_kernel(const float* __restrict__ W1,  const float* __restrict__ b1,
           const float* __restrict__ W2,  const float* __restrict__ b2,
           const float* __restrict__ Wd1, const float* __restrict__ bd1,
           const float* __restrict__ Wd2, const float* __restrict__ bd2,
           const float* __restrict__ ptimes, float* __restrict__ out)
{
    extern __shared__ float sm[];
    float* Z  = sm;                                  // [64][132] stage input zc
    float* G  = sm + TM * LDA_Z;                     // [64][260] hidden activations
    float* ZB = sm + TM * LDA_Z + TM * LDA_G;        // [64][132] substep base z
    int tid = threadIdx.x, lane = tid & 31, w = tid >> 5;
    int h  = lane >> 4;                              // 0..1
    int cg = lane & 15;                              // 0..15
    // 256-col GEMMs: 4x4 warp grid, thread = 8 rows (stride 2) x 4 cols
    int MG  = w & 3,  NG  = w >> 2;
    int rb1 = MG * 16 + h;
    int col1 = NG * 64 + cg * 4;
    // 128/64-col GEMMs: 8x2 warp grid, thread = 4 rows (stride 1) x 4(/2) cols
    int MG2 = w & 7,  NG2 = w >> 3;
    int rb2 = MG2 * 8 + h * 4;
    int col2 = NG2 * 64 + cg * 4;    // 128-col GEMM (4 cols/thread)
    int colD = NG2 * 32 + cg * 2;    // 64-col decode (2 cols/thread)
    int m0 = blockIdx.x * TM;

    float4 b1v  = __ldg(reinterpret_cast<const float4*>(&b1[col1]));
    float4 bd1v = __ldg(reinterpret_cast<const float4*>(&bd1[col1]));
    float4 b2v  = __ldg(reinterpret_cast<const float4*>(&b2[col2]));
    float2 bd2v = __ldg(reinterpret_cast<const float2*>(&bd2[colD]));

    // current z: this thread owns rows {rb2+i, i=0..3} x cols [col2, col2+4)
    float zr[4][4];
    #pragma unroll
    for (int i = 0; i < 4; ++i) {
        int row = rb2 + i;
        float4 v = *reinterpret_cast<const float4*>(&g_z0[(size_t)(m0 + row) * NLAT + col2]);
        zr[i][0]=v.x; zr[i][1]=v.y; zr[i][2]=v.z; zr[i][3]=v.w;
        *reinterpret_cast<float4*>(&Z[row * LDA_Z + col2]) = v;
    }
    __syncthreads();

    auto decode = [&](int tindex) {
        u64 a1[8][2];
        #pragma unroll
        for (int i = 0; i < 8; ++i) { a1[i][0] = 0; a1[i][1] = 0; }
        wgemmN<8, 2, 2>(Z, LDA_Z, NLAT, Wd1, NDEC, col1, rb1, a1);
        #pragma unroll
        for (int i = 0; i < 8; ++i) {
            int row = rb1 + 2 * i;
            float c0, c1, c2, c3;
            upk2(c0, c1, a1[i][0]); upk2(c2, c3, a1[i][1]);
            *reinterpret_cast<float4*>(&G[row * LDA_G + col1]) =
                make_float4(fmaxf(c0 + bd1v.x, 0.f), fmaxf(c1 + bd1v.y, 0.f),
                            fmaxf(c2 + bd1v.z, 0.f), fmaxf(c3 + bd1v.w, 0.f));
        }
        __syncthreads();
        u64 a2[4][1];
        #pragma unroll
        for (int i = 0; i < 4; ++i) a2[i][0] = 0;
        wgemmN<4, 1, 1>(G, LDA_G, NDEC, Wd2, NOBS, colD, rb2, a2);
        #pragma unroll
        for (int i = 0; i < 4; ++i) {
            int row = rb2 + i;
            float x, y; upk2(x, y, a2[i][0]);
            *reinterpret_cast<float2*>(
                &out[((size_t)tindex * NB + (m0 + row)) * NOBS + colD]) =
                make_float2(x + bd2v.x, y + bd2v.y);
        }
        __syncthreads();   // G reads done before next stage overwrites G
    };

    decode(0);

    #pragma unroll 1
    for (int iv = 0; iv < NT - 1; ++iv) {
        float dt = (__ldg(&ptimes[iv + 1]) - __ldg(&ptimes[iv])) * (1.0f / NSUB);
        #pragma unroll 1
        for (int ss = 0; ss < NSUB; ++ss) {
            // stash substep base z in padded SMEM (thread-private cells)
            #pragma unroll
            for (int i = 0; i < 4; ++i)
                *reinterpret_cast<float4*>(&ZB[(rb2 + i) * LDA_B + col2]) =
                    make_float4(zr[i][0], zr[i][1], zr[i][2], zr[i][3]);

            #pragma unroll 1
            for (int s = 0; s < 4; ++s) {
                float wt = (s == 0 || s == 3) ? dt * (1.0f / 6.0f) : dt * (1.0f / 3.0f);
                float ci = (s == 2) ? dt : 0.5f * dt;

                // g = tanh(zc @ W1 + b1)   [hardware tanh.approx]
                u64 a1[8][2];
                #pragma unroll
                for (int i = 0; i < 8; ++i) { a1[i][0] = 0; a1[i][1] = 0; }
                wgemmN<8, 2, 2>(Z, LDA_Z, NLAT, W1, NODE, col1, rb1, a1);
                #pragma unroll
                for (int i = 0; i < 8; ++i) {
                    int row = rb1 + 2 * i;
                    float c0, c1, c2, c3;
                    upk2(c0, c1, a1[i][0]); upk2(c2, c3, a1[i][1]);
                    *reinterpret_cast<float4*>(&G[row * LDA_G + col1]) =
                        make_float4(tanh_fast(c0 + b1v.x), tanh_fast(c1 + b1v.y),
                                    tanh_fast(c2 + b1v.z), tanh_fast(c3 + b1v.w));
                }
                __syncthreads();   // all GEMM1 (Z reads) + G writes complete

                // k = g @ W2 + b2 ; fold into RK4 accumulator and next stage input
                u64 a2[4][2];
                #pragma unroll
                for (int i = 0; i < 4; ++i) { a2[i][0] = 0; a2[i][1] = 0; }
                wgemmN<4, 1, 2>(G, LDA_G, NODE, W2, NLAT, col2, rb2, a2);
                #pragma unroll
                for (int i = 0; i < 4; ++i) {
                    int row = rb2 + i;
                    float k0, k1, k2, k3;
                    upk2(k0, k1, a2[i][0]); upk2(k2, k3, a2[i][1]);
                    k0 += b2v.x; k1 += b2v.y; k2 += b2v.z; k3 += b2v.w;
                    zr[i][0] += wt * k0; zr[i][1] += wt * k1;
                    zr[i][2] += wt * k2; zr[i][3] += wt * k3;
                    float4 v;
                    if (s < 3) {
                        float4 zb = *reinterpret_cast<const float4*>(&ZB[row * LDA_B + col2]);
                        v = make_float4(zb.x + ci * k0, zb.y + ci * k1,
                                        zb.z + ci * k2, zb.w + ci * k3);
                    } else {
                        v = make_float4(zr[i][0], zr[i][1], zr[i][2], zr[i][3]);
                    }
                    *reinterpret_cast<float4*>(&Z[row * LDA_Z + col2]) = v;
                }
                __syncthreads();   // Z consistent before next GEMM1 / decode
            }
        }
        decode(iv + 1);
    }
}

// -------------------- Launcher --------------------
extern "C" void kernel_launch(void* const* d_in, const int* in_sizes, int n_in,
                              void* d_out, int out_size)
{
    const float* obs    = (const float*)d_in[0];
    /* d_in[1] observed_times: unused by the reference computation */
    const float* ptimes = (const float*)d_in[2];
    const float* eps    = (const float*)d_in[3];
    const float* Wi2h   = (const float*)d_in[4];
    const float* bi2h   = (const float*)d_in[5];
    const float* Wh2o   = (const float*)d_in[6];
    const float* bh2o   = (const float*)d_in[7];
    const float* Wode1  = (const float*)d_in[8];
    const float* bode1  = (const float*)d_in[9];
    const float* Wode2  = (const float*)d_in[10];
    const float* bode2  = (const float*)d_in[11];
    const float* Wdec1  = (const float*)d_in[12];
    const float* bdec1  = (const float*)d_in[13];
    const float* Wdec2  = (const float*)d_in[14];
    const float* bdec2  = (const float*)d_in[15];
    float* out = (float*)d_out;

    const int SM_ENC = TM * LDA_A * 4;                               // 82944
    const int SM_ODE = (TM * LDA_Z + TM * LDA_G + TM * LDA_B) * 4;   // 134144

    cudaFuncSetAttribute(encoder_kernel, cudaFuncAttributeMaxDynamicSharedMemorySize, SM_ENC);
    cudaFuncSetAttribute(ode_kernel,     cudaFuncAttributeMaxDynamicSharedMemorySize, SM_ODE);

    dim3 grid(NB / TM);   // 128 CTAs

    encoder_kernel<<<grid, NTHREADS, SM_ENC>>>(obs, Wi2h, bi2h, Wh2o, bh2o, eps, out);
    ode_kernel<<<grid, NTHREADS, SM_ODE>>>(Wode1, bode1, Wode2, bode2,
                                           Wdec1, bdec1, Wdec2, bdec2, ptimes, out);
}

// round 16
// speedup vs baseline: 1.0021x; 1.0003x over previous
#include <cuda_runtime.h>
#include <math.h>

// Problem constants
#define NB    8192
#define NS    128
#define NT    64
#define NOBS  64
#define NLAT  128
#define NENC  256
#define NODE  256
#define NDEC  256
#define NSUB  4

#define TM       64     // batch rows per CTA
#define NTHREADS 512    // 16 warps, split over rows x cols (4x4 / 8x2 grids)

// padded leading dims: lda % 32 == 4 (floats) -> row pairs hit disjoint banks
#define LDA_Z 132
#define LDA_G 260
#define LDA_A 324
#define LDA_B 132       // ZB pad

typedef unsigned long long u64;

static __device__ float g_z0[NB * NLAT];   // z0 handoff (static scratch)

__device__ __forceinline__ u64 pk2(float x, float y) {
    u64 r; asm("mov.b64 %0, {%1, %2};" : "=l"(r) : "f"(x), "f"(y)); return r;
}
__device__ __forceinline__ void upk2(float& x, float& y, u64 v) {
    asm("mov.b64 {%0, %1}, %2;" : "=f"(x), "=f"(y) : "l"(v));
}
// packed fp32x2 fma -> SASS FFMA2 (2x fp32 rate)
__device__ __forceinline__ void ffma2(u64& d, u64 a, u64 b) {
    asm("fma.rn.f32x2 %0, %1, %2, %0;" : "+l"(d) : "l"(a), "l"(b));
}
__device__ __forceinline__ float f4c(const float4 v, int k) {
    return k == 0 ? v.x : k == 1 ? v.y : k == 2 ? v.z : v.w;
}
// hardware tanh (MUFU-class). ODE f-evals only; encoder keeps exact tanhf.
__device__ __forceinline__ float tanh_fast(float x) {
    float y; asm("tanh.approx.f32 %0, %1;" : "=f"(y) : "f"(x)); return y;
}

// Split-M+N warp GEMM with batched B loads (R8/R11 geometry, unroll-4 k-loop).
// Thread tile: NR rows {rbase + RS*i} x 2*PAIRS cols [col0,...).
// A: within a warp only 2 distinct rows per LDS.128 (h-split, lda%32==4 ->
// disjoint banks). B: 16 lanes read a contiguous slab, h-halves broadcast.
template<int NR, int RS, int PAIRS>
__device__ __forceinline__ void wgemmN(
    const float* __restrict__ As, int lda, int K,
    const float* __restrict__ Bg, int ldb, int col0,
    int rbase, u64 (&acc)[NR][PAIRS])
{
    #pragma unroll 4
    for (int k4 = 0; k4 < (K >> 2); ++k4) {
        // ---- batched B loads for all 4 kk of this k4 ----
        u64 bq[4][PAIRS];
        #pragma unroll
        for (int kk = 0; kk < 4; ++kk) {
            const float* bp = Bg + (size_t)(k4 * 4 + kk) * ldb + col0;
            if constexpr (PAIRS == 2) {
                ulonglong2 q = __ldg(reinterpret_cast<const ulonglong2*>(bp));
                bq[kk][0] = q.x; bq[kk][1] = q.y;
            } else {
                bq[kk][0] = __ldg(reinterpret_cast<const u64*>(bp));
            }
        }
        // ---- A fragments ----
        float4 av[NR];
        #pragma unroll
        for (int i = 0; i < NR; ++i)
            av[i] = *reinterpret_cast<const float4*>(&As[(rbase + RS * i) * lda + (k4 << 2)]);
        // ---- fma schedule ----
        #pragma unroll
        for (int kk = 0; kk < 4; ++kk) {
            #pragma unroll
            for (int i = 0; i < NR; ++i) {
                float a = f4c(av[i], kk);
                u64 aa = pk2(a, a);
                #pragma unroll
                for (int j = 0; j < PAIRS; ++j) ffma2(acc[i][j], aa, bq[kk][j]);
            }
        }
    }
}

// ==================== Persistent encoder: 128 RNN steps + head ====================
__global__ void __launch_bounds__(NTHREADS)
encoder_kernel(const float* __restrict__ obs,
               const float* __restrict__ Wi2h, const float* __restrict__ bi2h,
               const float* __restrict__ Wh2o, const float* __restrict__ bh2o,
               const float* __restrict__ eps, float* __restrict__ out)
{
    extern __shared__ float A[];                 // [64][324]: [x(64) | h(256) | pad]
    int tid = threadIdx.x, lane = tid & 31, w = tid >> 5;
    int h  = lane >> 4;                          // 0..1
    int cg = lane & 15;                          // 0..15
    int MG = w & 3, NG = w >> 2;                 // 4 x 4 warp grid
    int rbase = MG * 16 + h;                     // rows rbase + 2i, i=0..7
    int col1  = NG * 64 + cg * 4;                // 4-col slab in 256-col outputs
    int m0 = blockIdx.x * TM;

    // zero the h region
    for (int i = tid; i < TM * NENC / 4; i += NTHREADS) {
        int m = i >> 6, k = (i & 63) << 2;
        *reinterpret_cast<float4*>(&A[m * LDA_A + NOBS + k]) = make_float4(0, 0, 0, 0);
    }
    float4 bi = __ldg(reinterpret_cast<const float4*>(&bi2h[col1]));

    // load x for t = NS-1  (64 rows x 16 float4 = 1024 float4, 2 per thread)
    #pragma unroll
    for (int j = 0; j < 2; ++j) {
        int idx = tid + j * NTHREADS;
        int row = idx >> 4, f = idx & 15;
        *reinterpret_cast<float4*>(&A[row * LDA_A + f * 4]) =
            __ldg(reinterpret_cast<const float4*>(
                &obs[((size_t)(m0 + row) * NS + (NS - 1)) * NOBS + f * 4]));
    }
    __syncthreads();

    #pragma unroll 1
    for (int s = 0; s < NS; ++s) {
        u64 acc[8][2];
        #pragma unroll
        for (int i = 0; i < 8; ++i) { acc[i][0] = 0; acc[i][1] = 0; }
        wgemmN<8, 2, 2>(A, LDA_A, NOBS + NENC, Wi2h, NENC, col1, rbase, acc);

        // prefetch next step's x while waiting at the barrier
        float4 xp[2];
        if (s + 1 < NS) {
            #pragma unroll
            for (int j = 0; j < 2; ++j) {
                int idx = tid + j * NTHREADS;
                int row = idx >> 4, f = idx & 15;
                xp[j] = __ldg(reinterpret_cast<const float4*>(
                    &obs[((size_t)(m0 + row) * NS + (NS - 2 - s)) * NOBS + f * 4]));
            }
        }
        __syncthreads();   // all A reads done

        #pragma unroll
        for (int i = 0; i < 8; ++i) {
            int row = rbase + 2 * i;
            float c0, c1, c2, c3;
            upk2(c0, c1, acc[i][0]); upk2(c2, c3, acc[i][1]);
            *reinterpret_cast<float4*>(&A[row * LDA_A + NOBS + col1]) =
                make_float4(tanhf(c0 + bi.x), tanhf(c1 + bi.y),
                            tanhf(c2 + bi.z), tanhf(c3 + bi.w));
        }
        if (s + 1 < NS) {
            #pragma unroll
            for (int j = 0; j < 2; ++j) {
                int idx = tid + j * NTHREADS;
                int row = idx >> 4, f = idx & 15;
                *reinterpret_cast<float4*>(&A[row * LDA_A + f * 4]) = xp[j];
            }
        }
        __syncthreads();
    }

    // head: O = h @ Wh2o + b  (into A cols 0..255 after reads complete)
    u64 acc[8][2];
    #pragma unroll
    for (int i = 0; i < 8; ++i) { acc[i][0] = 0; acc[i][1] = 0; }
    wgemmN<8, 2, 2>(A + NOBS, LDA_A, NENC, Wh2o, 2 * NLAT, col1, rbase, acc);
    float4 bh = __ldg(reinterpret_cast<const float4*>(&bh2o[col1]));
    __syncthreads();
    #pragma unroll
    for (int i = 0; i < 8; ++i) {
        int row = rbase + 2 * i;
        float c0, c1, c2, c3;
        upk2(c0, c1, acc[i][0]); upk2(c2, c3, acc[i][1]);
        *reinterpret_cast<float4*>(&A[row * LDA_A + col1]) =
            make_float4(c0 + bh.x, c1 + bh.y, c2 + bh.z, c3 + bh.w);
    }
    __syncthreads();

    // z0 = mean + eps * exp(0.5*logvar); emit mean/logvar
    const size_t MEAN_OFF = (size_t)NT * NB * NOBS;
    const size_t LV_OFF   = MEAN_OFF + (size_t)NB * NLAT;
    for (int i = tid; i < TM * NLAT; i += NTHREADS) {
        int m = i >> 7, l = i & (NLAT - 1);
        float mean = A[m * LDA_A + l];
        float lv   = A[m * LDA_A + NLAT + l];
        float z0   = mean + __ldg(&eps[(size_t)(m0 + m) * NLAT + l]) * expf(0.5f * lv);
        g_z0[(size_t)(m0 + m) * NLAT + l] = z0;
        out[MEAN_OFF + (size_t)(m0 + m) * NLAT + l] = mean;
        out[LV_OFF   + (size_t)(m0 + m) * NLAT + l] = lv;
    }
}

// ==================== Persistent ODE: 63x4 RK4 substeps + 64 decodes ====================
__global__ void __launch_bounds__(NTHREADS)
ode_kernel(const float* __restrict__ W1,  const float* __restrict__ b1,
           const float* __restrict__ W2,  const float* __restrict__ b2,
           const float* __restrict__ Wd1, const float* __restrict__ bd1,
           const float* __restrict__ Wd2, const float* __restrict__ bd2,
           const float* __restrict__ ptimes, float* __restrict__ out)
{
    extern __shared__ float sm[];
    float* Z  = sm;                                  // [64][132] stage input zc
    float* G  = sm + TM * LDA_Z;                     // [64][260] hidden activations
    float* ZB = sm + TM * LDA_Z + TM * LDA_G;        // [64][132] substep base z
    int tid = threadIdx.x, lane = tid & 31, w = tid >> 5;
    int h  = lane >> 4;                              // 0..1
    int cg = lane & 15;                              // 0..15
    // 256-col GEMMs: 4x4 warp grid, thread = 8 rows (stride 2) x 4 cols
    int MG  = w & 3,  NG  = w >> 2;
    int rb1 = MG * 16 + h;
    int col1 = NG * 64 + cg * 4;
    // 128/64-col GEMMs: 8x2 warp grid, thread = 4 rows (stride 1) x 4(/2) cols
    int MG2 = w & 7,  NG2 = w >> 3;
    int rb2 = MG2 * 8 + h * 4;
    int col2 = NG2 * 64 + cg * 4;    // 128-col GEMM (4 cols/thread)
    int colD = NG2 * 32 + cg * 2;    // 64-col decode (2 cols/thread)
    int m0 = blockIdx.x * TM;

    float4 b1v  = __ldg(reinterpret_cast<const float4*>(&b1[col1]));
    float4 bd1v = __ldg(reinterpret_cast<const float4*>(&bd1[col1]));
    float4 b2v  = __ldg(reinterpret_cast<const float4*>(&b2[col2]));
    float2 bd2v = __ldg(reinterpret_cast<const float2*>(&bd2[colD]));

    // current z: this thread owns rows {rb2+i, i=0..3} x cols [col2, col2+4)
    float zr[4][4];
    #pragma unroll
    for (int i = 0; i < 4; ++i) {
        int row = rb2 + i;
        float4 v = *reinterpret_cast<const float4*>(&g_z0[(size_t)(m0 + row) * NLAT + col2]);
        zr[i][0]=v.x; zr[i][1]=v.y; zr[i][2]=v.z; zr[i][3]=v.w;
        *reinterpret_cast<float4*>(&Z[row * LDA_Z + col2]) = v;
    }
    __syncthreads();

    auto decode = [&](int tindex) {
        u64 a1[8][2];
        #pragma unroll
        for (int i = 0; i < 8; ++i) { a1[i][0] = 0; a1[i][1] = 0; }
        wgemmN<8, 2, 2>(Z, LDA_Z, NLAT, Wd1, NDEC, col1, rb1, a1);
        #pragma unroll
        for (int i = 0; i < 8; ++i) {
            int row = rb1 + 2 * i;
            float c0, c1, c2, c3;
            upk2(c0, c1, a1[i][0]); upk2(c2, c3, a1[i][1]);
            *reinterpret_cast<float4*>(&G[row * LDA_G + col1]) =
                make_float4(fmaxf(c0 + bd1v.x, 0.f), fmaxf(c1 + bd1v.y, 0.f),
                            fmaxf(c2 + bd1v.z, 0.f), fmaxf(c3 + bd1v.w, 0.f));
        }
        __syncthreads();
        u64 a2[4][1];
        #pragma unroll
        for (int i = 0; i < 4; ++i) a2[i][0] = 0;
        wgemmN<4, 1, 1>(G, LDA_G, NDEC, Wd2, NOBS, colD, rb2, a2);
        #pragma unroll
        for (int i = 0; i < 4; ++i) {
            int row = rb2 + i;
            float x, y; upk2(x, y, a2[i][0]);
            *reinterpret_cast<float2*>(
                &out[((size_t)tindex * NB + (m0 + row)) * NOBS + colD]) =
                make_float2(x + bd2v.x, y + bd2v.y);
        }
        __syncthreads();   // G reads done before next stage overwrites G
    };

    decode(0);

    #pragma unroll 1
    for (int iv = 0; iv < NT - 1; ++iv) {
        float dt = (__ldg(&ptimes[iv + 1]) - __ldg(&ptimes[iv])) * (1.0f / NSUB);
        #pragma unroll 1
        for (int ss = 0; ss < NSUB; ++ss) {
            // stash substep base z in padded SMEM (thread-private cells)
            #pragma unroll
            for (int i = 0; i < 4; ++i)
                *reinterpret_cast<float4*>(&ZB[(rb2 + i) * LDA_B + col2]) =
                    make_float4(zr[i][0], zr[i][1], zr[i][2], zr[i][3]);

            #pragma unroll 1
            for (int s = 0; s < 4; ++s) {
                float wt = (s == 0 || s == 3) ? dt * (1.0f / 6.0f) : dt * (1.0f / 3.0f);
                float ci = (s == 2) ? dt : 0.5f * dt;

                // g = tanh(zc @ W1 + b1)   [hardware tanh.approx]
                u64 a1[8][2];
                #pragma unroll
                for (int i = 0; i < 8; ++i) { a1[i][0] = 0; a1[i][1] = 0; }
                wgemmN<8, 2, 2>(Z, LDA_Z, NLAT, W1, NODE, col1, rb1, a1);
                #pragma unroll
                for (int i = 0; i < 8; ++i) {
                    int row = rb1 + 2 * i;
                    float c0, c1, c2, c3;
                    upk2(c0, c1, a1[i][0]); upk2(c2, c3, a1[i][1]);
                    *reinterpret_cast<float4*>(&G[row * LDA_G + col1]) =
                        make_float4(tanh_fast(c0 + b1v.x), tanh_fast(c1 + b1v.y),
                                    tanh_fast(c2 + b1v.z), tanh_fast(c3 + b1v.w));
                }
                __syncthreads();   // all GEMM1 (Z reads) + G writes complete

                // k = g @ W2 + b2 ; fold into RK4 accumulator and next stage input
                u64 a2[4][2];
                #pragma unroll
                for (int i = 0; i < 4; ++i) { a2[i][0] = 0; a2[i][1] = 0; }
                wgemmN<4, 1, 2>(G, LDA_G, NODE, W2, NLAT, col2, rb2, a2);
                #pragma unroll
                for (int i = 0; i < 4; ++i) {
                    int row = rb2 + i;
                    float k0, k1, k2, k3;
                    upk2(k0, k1, a2[i][0]); upk2(k2, k3, a2[i][1]);
                    k0 += b2v.x; k1 += b2v.y; k2 += b2v.z; k3 += b2v.w;
                    zr[i][0] += wt * k0; zr[i][1] += wt * k1;
                    zr[i][2] += wt * k2; zr[i][3] += wt * k3;
                    float4 v;
                    if (s < 3) {
                        float4 zb = *reinterpret_cast<const float4*>(&ZB[row * LDA_B + col2]);
                        v = make_float4(zb.x + ci * k0, zb.y + ci * k1,
                                        zb.z + ci * k2, zb.w + ci * k3);
                    } else {
                        v = make_float4(zr[i][0], zr[i][1], zr[i][2], zr[i][3]);
                    }
                    *reinterpret_cast<float4*>(&Z[row * LDA_Z + col2]) = v;
                }
                __syncthreads();   // Z consistent before next GEMM1 / decode
            }
        }
        decode(iv + 1);
    }
}

// -------------------- Launcher --------------------
extern "C" void kernel_launch(void* const* d_in, const int* in_sizes, int n_in,
                              void* d_out, int out_size)
{
    const float* obs    = (const float*)d_in[0];
    /* d_in[1] observed_times: unused by the reference computation */
    const float* ptimes = (const float*)d_in[2];
    const float* eps    = (const float*)d_in[3];
    const float* Wi2h   = (const float*)d_in[4];
    const float* bi2h   = (const float*)d_in[5];
    const float* Wh2o   = (const float*)d_in[6];
    const float* bh2o   = (const float*)d_in[7];
    const float* Wode1  = (const float*)d_in[8];
    const float* bode1  = (const float*)d_in[9];
    const float* Wode2  = (const float*)d_in[10];
    const float* bode2  = (const float*)d_in[11];
    const float* Wdec1  = (const float*)d_in[12];
    const float* bdec1  = (const float*)d_in[13];
    const float* Wdec2  = (const float*)d_in[14];
    const float* bdec2  = (const float*)d_in[15];
    float* out = (float*)d_out;

    const int SM_ENC = TM * LDA_A * 4;                               // 82944
    const int SM_ODE = (TM * LDA_Z + TM * LDA_G + TM * LDA_B) * 4;   // 134144

    cudaFuncSetAttribute(encoder_kernel, cudaFuncAttributeMaxDynamicSharedMemorySize, SM_ENC);
    cudaFuncSetAttribute(ode_kernel,     cudaFuncAttributeMaxDynamicSharedMemorySize, SM_ODE);

    dim3 grid(NB / TM);   // 128 CTAs

    encoder_kernel<<<grid, NTHREADS, SM_ENC>>>(obs, Wi2h, bi2h, Wh2o, bh2o, eps, out);
    ode_kernel<<<grid, NTHREADS, SM_ODE>>>(Wode1, bode1, Wode2, bode2,
                                           Wdec1, bdec1, Wdec2, bdec2, ptimes, out);
}